// round 7
// baseline (speedup 1.0000x reference)
#include <cuda_runtime.h>
#include <cstdint>

// TMA bulk-async pipeline + DYNAMIC tile scheduling (global atomic ticket).
// 148 persistent CTAs (1/SM), 1024 threads.
//   warp 31 lane 0 = producer: grabs tile tickets, issues cp.async.bulk
//                    (pred +16B shift, x, y) into a 4-stage SMEM ring,
//                    publishes tile-id / -1 sentinel per stage.
//   warps 0..30    = consumers: acquire-wait full, reduce tile from SMEM,
//                    warp-elected empty arrive; exit on sentinel.
// Work stealing kills the static-partition tail (spr floor ~1.10).
// Deterministic-enough: summation order varies run-to-run, value within fp32
// noise (rel tolerance 1e-3). Counters reset in finalize -> graph-replay safe.

static constexpr int CTAS        = 148;
static constexpr int THREADS     = 1024;
static constexpr int STAGES      = 4;
static constexpr int TILE_FLOATS = 4096;
static constexpr int TILE_BYTES  = TILE_FLOATS * 4;               // 16384
static constexpr int TILE_F4     = TILE_FLOATS / 4;               // 1024
static constexpr int NCONS_WARPS = 31;
static constexpr int NCONS       = NCONS_WARPS * 32;              // 992
static constexpr int PRED_BYTES  = TILE_BYTES + 16;               // shift slack
static constexpr int STAGE_BYTES = PRED_BYTES + 2 * TILE_BYTES;   // 49168
static constexpr int X_OFF       = PRED_BYTES;
static constexpr int Y_OFF       = PRED_BYTES + TILE_BYTES;
static constexpr int BAR_OFF     = STAGES * STAGE_BYTES;          // 196672
static constexpr int IDX_OFF     = BAR_OFF + STAGES * 16;         // 196736
static constexpr int SMEM_SIZE   = IDX_OFF + STAGES * 4;          // 196752

__device__ float        g_partials[CTAS];
__device__ unsigned int g_done_count;   // zero-init; reset each call
__device__ unsigned int g_ticket;       // zero-init; reset each call

__device__ __forceinline__ uint32_t smem_u32(const void* p) {
    uint32_t a;
    asm("{ .reg .u64 t; cvta.to.shared.u64 t, %1; cvt.u32.u64 %0, t; }" : "=r"(a) : "l"(p));
    return a;
}
__device__ __forceinline__ void mbar_init(uint32_t m, uint32_t cnt) {
    asm volatile("mbarrier.init.shared.b64 [%0], %1;" :: "r"(m), "r"(cnt) : "memory");
}
__device__ __forceinline__ void mbar_expect_tx(uint32_t m, uint32_t bytes) {
    asm volatile("mbarrier.arrive.expect_tx.release.cta.shared::cta.b64 _, [%0], %1;"
                 :: "r"(m), "r"(bytes) : "memory");
}
__device__ __forceinline__ void mbar_arrive(uint32_t m) {
    asm volatile("mbarrier.arrive.release.cta.shared::cta.b64 _, [%0];" :: "r"(m) : "memory");
}
__device__ __forceinline__ void mbar_wait(uint32_t m, uint32_t parity) {
    asm volatile(
        "{\n\t"
        ".reg .pred P;\n\t"
        "LAB_%=:\n\t"
        "mbarrier.try_wait.parity.acquire.cta.shared::cta.b64 P, [%0], %1, 0x989680;\n\t"
        "@!P bra LAB_%=;\n\t"
        "}"
        :: "r"(m), "r"(parity) : "memory");
}
__device__ __forceinline__ void bulk_g2s(uint32_t dst, const void* src, uint32_t bytes, uint32_t mbar) {
    asm volatile(
        "cp.async.bulk.shared::cluster.global.mbarrier::complete_tx::bytes [%0], [%1], %2, [%3];"
        :: "r"(dst), "l"(src), "r"(bytes), "r"(mbar) : "memory");
}
__device__ __forceinline__ void st_s32(uint32_t addr, int v) {
    asm volatile("st.shared.b32 [%0], %1;" :: "r"(addr), "r"(v) : "memory");
}
__device__ __forceinline__ int ld_s32(uint32_t addr) {
    int v;
    asm volatile("ld.shared.b32 %0, [%1];" : "=r"(v) : "r"(addr) : "memory");
    return v;
}

__global__ __launch_bounds__(THREADS, 1) void trajloss_ticket_kernel(
    const float* __restrict__ pred,   // N+1
    const float* __restrict__ xs,     // N
    const float* __restrict__ ys,     // N
    float* __restrict__ out,
    int n,
    int nTiles)                       // = n/TILE_FLOATS - 1 (last tile -> remainder)
{
    extern __shared__ __align__(128) char smem[];
    const uint32_t sbase = smem_u32(smem);
    const int tid  = threadIdx.x;
    const int lane = tid & 31;
    const int wid  = tid >> 5;

    if (tid == 0) {
        #pragma unroll
        for (int s = 0; s < STAGES; s++) {
            mbar_init(sbase + BAR_OFF + s * 16,     1);            // full
            mbar_init(sbase + BAR_OFF + s * 16 + 8, NCONS_WARPS);  // empty
        }
    }
    __syncthreads();

    float acc0 = 0.0f, acc1 = 0.0f;

    if (wid == NCONS_WARPS) {
        // ---------------- producer (highest wid, lane 0) ----------------
        if (lane == 0) {
            int k = 0;
            for (;;) {
                int s = k & (STAGES - 1);
                uint32_t ph = 1u ^ (uint32_t)((k >> 2) & 1);      // first pass free
                uint32_t full_b  = sbase + BAR_OFF + s * 16;
                uint32_t empty_b = full_b + 8;
                mbar_wait(empty_b, ph);

                unsigned int t = atomicAdd(&g_ticket, 1u);
                if (t >= (unsigned int)nTiles) {
                    st_s32(sbase + IDX_OFF + s * 4, -1);          // sentinel
                    mbar_arrive(full_b);                          // release, flips now
                    break;
                }
                st_s32(sbase + IDX_OFF + s * 4, (int)t);
                mbar_expect_tx(full_b, STAGE_BYTES);              // release + tx
                uint32_t stg = sbase + s * STAGE_BYTES;
                long off = (long)t * TILE_FLOATS;
                bulk_g2s(stg,         pred + off, PRED_BYTES, full_b);
                bulk_g2s(stg + X_OFF, xs   + off, TILE_BYTES, full_b);
                bulk_g2s(stg + Y_OFF, ys   + off, TILE_BYTES, full_b);
                k++;
            }
        }
    } else {
        // ---------------- consumers (warps 0..30) ----------------
        const int ct = tid;                                       // 0..991
        int k = 0;
        for (;;) {
            int s = k & (STAGES - 1);
            uint32_t ph = (uint32_t)((k >> 2) & 1);
            uint32_t full_b  = sbase + BAR_OFF + s * 16;
            uint32_t empty_b = full_b + 8;
            mbar_wait(full_b, ph);                                // acquire

            if (ld_s32(sbase + IDX_OFF + s * 4) < 0) break;       // sentinel

            const char* stg = smem + s * STAGE_BYTES;
            const float4* p4 = reinterpret_cast<const float4*>(stg);
            const float*  pf = reinterpret_cast<const float*>(stg);
            const float4* x4 = reinterpret_cast<const float4*>(stg + X_OFF);
            const float4* y4 = reinterpret_cast<const float4*>(stg + Y_OFF);

            #pragma unroll 2
            for (int j = ct; j < TILE_F4; j += NCONS) {
                float4 p  = p4[j];
                float4 xv = x4[j];
                float4 yv = y4[j];
                float  pn = pf[4 * j + 4];                        // +16B slack

                float dx0 = xv.x - p.x, dx1 = xv.y - p.y;
                float dx2 = xv.z - p.z, dx3 = xv.w - p.w;
                float dy0 = yv.x - p.y, dy1 = yv.y - p.z;
                float dy2 = yv.z - p.w, dy3 = yv.w - pn;

                acc0 = fmaf(dx0, dx0, acc0); acc1 = fmaf(dy0, dy0, acc1);
                acc0 = fmaf(dx1, dx1, acc0); acc1 = fmaf(dy1, dy1, acc1);
                acc0 = fmaf(dx2, dx2, acc0); acc1 = fmaf(dy2, dy2, acc1);
                acc0 = fmaf(dx3, dx3, acc0); acc1 = fmaf(dy3, dy3, acc1);
            }
            __syncwarp();
            if (lane == 0) mbar_arrive(empty_b);
            k++;
        }
    }

    // ---- remainder: last tile + final shifted element, bounds-checked ----
    {
        long base = (long)nTiles * TILE_FLOATS;
        for (long i = base + (long)blockIdx.x * THREADS + tid; i < n;
             i += (long)CTAS * THREADS) {
            float dx = xs[i] - pred[i];
            float dy = ys[i] - pred[i + 1];
            acc0 = fmaf(dx, dx, acc0);
            acc1 = fmaf(dy, dy, acc1);
        }
    }

    float acc = acc0 + acc1;

    // ---------------- intra-block reduction ----------------
    #pragma unroll
    for (int off = 16; off > 0; off >>= 1)
        acc += __shfl_xor_sync(0xFFFFFFFFu, acc, off);

    __shared__ float warp_sums[32];
    __shared__ bool  is_last;
    __syncthreads();                 // pipeline drained before smem reuse
    if (lane == 0) warp_sums[wid] = acc;
    __syncthreads();

    if (wid == 0) {
        float v = warp_sums[lane];
        #pragma unroll
        for (int off = 16; off > 0; off >>= 1)
            v += __shfl_xor_sync(0xFFFFFFFFu, v, off);
        if (lane == 0) {
            g_partials[blockIdx.x] = v;
            __threadfence();
            unsigned int prev = atomicAdd(&g_done_count, 1u);
            is_last = (prev == (unsigned int)(CTAS - 1));
        }
    }
    __syncthreads();

    // ---------------- last block finalizes ----------------
    if (is_last) {
        float t = (tid < CTAS) ? g_partials[tid] : 0.0f;

        #pragma unroll
        for (int off = 16; off > 0; off >>= 1)
            t += __shfl_xor_sync(0xFFFFFFFFu, t, off);

        if (lane == 0) warp_sums[wid] = t;
        __syncthreads();

        if (wid == 0) {
            float v = warp_sums[lane];
            #pragma unroll
            for (int off = 16; off > 0; off >>= 1)
                v += __shfl_xor_sync(0xFFFFFFFFu, v, off);
            if (lane == 0) {
                out[0] = v;
                g_ticket     = 0;    // graph-replay safe resets
                g_done_count = 0;
            }
        }
    }
}

extern "C" void kernel_launch(void* const* d_in, const int* in_sizes, int n_in,
                              void* d_out, int out_size)
{
    const float* pred = (const float*)d_in[0];   // N+1
    const float* xs   = (const float*)d_in[1];   // N
    const float* ys   = (const float*)d_in[2];   // N
    float* out        = (float*)d_out;

    int n = in_sizes[1];
    int nTiles = n / TILE_FLOATS - 1;   // last tile via remainder (OOB-safe)

    cudaFuncSetAttribute(trajloss_ticket_kernel,
                         cudaFuncAttributeMaxDynamicSharedMemorySize, SMEM_SIZE);
    trajloss_ticket_kernel<<<CTAS, THREADS, SMEM_SIZE>>>(pred, xs, ys, out, n, nTiles);
}